// round 4
// baseline (speedup 1.0000x reference)
#include <cuda_runtime.h>

// ---------------------------------------------------------------------------
// Net_VIF: 6 chained quadrilinear (4D) LUT interpolations, fully fused,
// bit-exact vs the JAX reference (sequential rn ops, corner order c=0..15).
//
// R3: lane-cooperative corner fetch. LUTs repacked to a 32B-aligned PAIR
// layout so the two b3-adjacent corners of one pixel are fetched by a lane
// PAIR in one LDG round -> each LDG.128's 32 lanes touch 16 cache lines
// instead of 32, halving L1tex wavefront traffic (the measured bottleneck
// class). Values are exchanged with shfl_xor; accumulation order and
// rounding are unchanged (bit movement only).
// ---------------------------------------------------------------------------

#define D   17
#define D2  289
#define D3  4913
#define D4  83521
#define N_LUTS 6

// pair layout: entry e = pair_index*2 + b3 ; pair_index = ((i0*D+i1)*D+i2)*D+i3
// 6 * 83521 * 2 * 16B = ~16 MB static device scratch (allocation-free).
__device__ __align__(128) float4 g_lutP[N_LUTS][D4 * 2];

// Single merged prepass (1 launch): blockIdx.y selects the LUT.
__global__ void lut_pack_kernel(const float* __restrict__ s0, const float* __restrict__ s1,
                                const float* __restrict__ s2, const float* __restrict__ s3,
                                const float* __restrict__ s4, const float* __restrict__ s5) {
    int i = blockIdx.x * blockDim.x + threadIdx.x;
    if (i >= D4) return;
    int which = blockIdx.y;
    const float* src = (which == 0) ? s0 : (which == 1) ? s1 : (which == 2) ? s2
                     : (which == 3) ? s3 : (which == 4) ? s4 : s5;
    bool c4 = (which != 5);
    float4 a;
    a.x = src[i];
    a.y = src[D4 + i];
    a.z = src[2 * D4 + i];
    a.w = c4 ? src[3 * D4 + i] : 0.0f;
    float4 b = make_float4(0.0f, 0.0f, 0.0f, 0.0f);
    if ((i % D) < D - 1) {
        b.x = src[i + 1];
        b.y = src[D4 + i + 1];
        b.z = src[2 * D4 + i + 1];
        b.w = c4 ? src[3 * D4 + i + 1] : 0.0f;
    }
    g_lutP[which][2 * i]     = a;
    g_lutP[which][2 * i + 1] = b;
}

__device__ __forceinline__ int pair_base(float4 xs) {
    float t0 = __saturatef(xs.x) * 16.0f;
    float t1 = __saturatef(xs.y) * 16.0f;
    float t2 = __saturatef(xs.z) * 16.0f;
    float t3 = __saturatef(xs.w) * 16.0f;
    int i0 = min((int)t0, D - 2);
    int i1 = min((int)t1, D - 2);
    int i2 = min((int)t2, D - 2);
    int i3 = min((int)t3, D - 2);
    return ((i0 * D + i1) * D + i2) * D + i3;
}

// Compile-time corner offset within the pair-index space (b3 excluded).
__device__ __forceinline__ int corner_off(int j) {
    return (j & 1) * D3 + ((j >> 1) & 1) * D2 + ((j >> 2) & 1) * D;
}

// One LUT stage for the whole warp (32 pixels), cooperative fetch.
//  Round A: lane l loads pixel (l & ~1) with b3 = (l & 1).
//  Round B: lane l loads pixel (l | 1)  with b3 = 1 - (l & 1).
// => every lane's OWN loads are the b3=0 half of its OWN pixel; the b3=1
//    half arrives from the partner lane via one shfl_xor per float.
__device__ __forceinline__ float4 coop_stage(const float4* __restrict__ lut,
                                             float4 x, int lane) {
    const unsigned FULL = 0xffffffffu;
    const int half = lane & 1;
    const int srcA = lane & ~1;
    const int srcB = lane | 1;

    // Served pixels' inputs (bitwise copies of the owners' x).
    float4 xa, xb;
    xa.x = __shfl_sync(FULL, x.x, srcA);
    xa.y = __shfl_sync(FULL, x.y, srcA);
    xa.z = __shfl_sync(FULL, x.z, srcA);
    xa.w = __shfl_sync(FULL, x.w, srcA);
    xb.x = __shfl_sync(FULL, x.x, srcB);
    xb.y = __shfl_sync(FULL, x.y, srcB);
    xb.z = __shfl_sync(FULL, x.z, srcB);
    xb.w = __shfl_sync(FULL, x.w, srcB);

    const int baseA = pair_base(xa);
    const int baseB = pair_base(xb);
    const int b3A = half;        // round A b3 for this lane
    const int b3B = 1 - half;    // round B b3 for this lane

    // Issue all 16 loads (adjacent lanes of a pair hit the same 128B line).
    float4 vA[8], vB[8];
#pragma unroll
    for (int j = 0; j < 8; ++j)
        vA[j] = __ldg(lut + ((baseA + corner_off(j)) * 2 + b3A));
#pragma unroll
    for (int j = 0; j < 8; ++j)
        vB[j] = __ldg(lut + ((baseB + corner_off(j)) * 2 + b3B));

    // Weights from OWN x, in the reference's exact rounding order:
    // w[c] = ((w0*w1)*w2)*w3 with sequential rn multiplies.
    float t0 = __saturatef(x.x) * 16.0f;
    float t1 = __saturatef(x.y) * 16.0f;
    float t2 = __saturatef(x.z) * 16.0f;
    float t3 = __saturatef(x.w) * 16.0f;
    int i0 = min((int)t0, D - 2);
    int i1 = min((int)t1, D - 2);
    int i2 = min((int)t2, D - 2);
    int i3 = min((int)t3, D - 2);
    float f0 = t0 - (float)i0;
    float f1 = t1 - (float)i1;
    float f2 = t2 - (float)i2;
    float f3 = t3 - (float)i3;
    float g0 = 1.0f - f0, g1 = 1.0f - f1, g2 = 1.0f - f2, g3 = 1.0f - f3;

    float p01[4];
    p01[0] = __fmul_rn(g0, g1);
    p01[1] = __fmul_rn(f0, g1);
    p01[2] = __fmul_rn(g0, f1);
    p01[3] = __fmul_rn(f0, f1);
    float p012[8];
#pragma unroll
    for (int j = 0; j < 4; ++j) {
        p012[j]     = __fmul_rn(p01[j], g2);
        p012[4 + j] = __fmul_rn(p01[j], f2);
    }
    float w0[8], w1[8];
#pragma unroll
    for (int j = 0; j < 8; ++j) {
        w0[j] = __fmul_rn(p012[j], g3);   // corners c = j      (b3 = 0)
        w1[j] = __fmul_rn(p012[j], f3);   // corners c = 8 + j  (b3 = 1)
    }

    // Accumulate c = 0..7 from OWN loads (even lanes: vA; odd lanes: vB).
    float4 acc = make_float4(0.0f, 0.0f, 0.0f, 0.0f);
#pragma unroll
    for (int j = 0; j < 8; ++j) {
        float ox = half ? vB[j].x : vA[j].x;
        float oy = half ? vB[j].y : vA[j].y;
        float oz = half ? vB[j].z : vA[j].z;
        float ow = half ? vB[j].w : vA[j].w;
        acc.x = __fadd_rn(acc.x, __fmul_rn(ox, w0[j]));
        acc.y = __fadd_rn(acc.y, __fmul_rn(oy, w0[j]));
        acc.z = __fadd_rn(acc.z, __fmul_rn(oz, w0[j]));
        acc.w = __fadd_rn(acc.w, __fmul_rn(ow, w0[j]));
    }

    // Exchange: each lane sends the half its partner owns, receives its own
    // pixel's b3=1 corners; accumulate c = 8..15 in order.
#pragma unroll
    for (int j = 0; j < 8; ++j) {
        float sx = half ? vA[j].x : vB[j].x;
        float sy = half ? vA[j].y : vB[j].y;
        float sz = half ? vA[j].z : vB[j].z;
        float sw = half ? vA[j].w : vB[j].w;
        float rx = __shfl_xor_sync(FULL, sx, 1);
        float ry = __shfl_xor_sync(FULL, sy, 1);
        float rz = __shfl_xor_sync(FULL, sz, 1);
        float rw = __shfl_xor_sync(FULL, sw, 1);
        acc.x = __fadd_rn(acc.x, __fmul_rn(rx, w1[j]));
        acc.y = __fadd_rn(acc.y, __fmul_rn(ry, w1[j]));
        acc.z = __fadd_rn(acc.z, __fmul_rn(rz, w1[j]));
        acc.w = __fadd_rn(acc.w, __fmul_rn(rw, w1[j]));
    }
    return acc;
}

__global__ void __launch_bounds__(256, 2)
net_vif_kernel(const float* __restrict__ vi,
               const float* __restrict__ ir,
               float* __restrict__ out) {
    const int HW = 512 * 512;                  // 1<<18
    int p  = blockIdx.x * blockDim.x + threadIdx.x;
    int hw = p & (HW - 1);
    int b  = p >> 18;
    int lane = threadIdx.x & 31;

    const float* vb = vi + (size_t)b * 3 * HW + hw;
    float4 x;
    x.x = vb[0];
    x.y = vb[HW];
    x.z = vb[2 * HW];
    x.w = ir[(size_t)b * HW + hw];

    x = coop_stage(g_lutP[0], x, lane);   // lut8
    x = coop_stage(g_lutP[1], x, lane);   // lut00
    x = coop_stage(g_lutP[2], x, lane);   // lut01
    x = coop_stage(g_lutP[3], x, lane);   // lut02
    x = coop_stage(g_lutP[4], x, lane);   // lut03
    x = coop_stage(g_lutP[5], x, lane);   // lutpgf (no final clip)

    float* ob = out + (size_t)b * 3 * HW + hw;
    ob[0]      = x.x;
    ob[HW]     = x.y;
    ob[2 * HW] = x.z;
}

extern "C" void kernel_launch(void* const* d_in, const int* in_sizes, int n_in,
                              void* d_out, int out_size) {
    const float* vi = (const float*)d_in[0];   // [8,3,512,512]
    const float* ir = (const float*)d_in[1];   // [8,1,512,512]

    dim3 pg((D4 + 255) / 256, N_LUTS);
    lut_pack_kernel<<<pg, 256>>>((const float*)d_in[2], (const float*)d_in[3],
                                 (const float*)d_in[4], (const float*)d_in[5],
                                 (const float*)d_in[6], (const float*)d_in[7]);

    const int total = 8 * 512 * 512;           // 2,097,152
    net_vif_kernel<<<total / 256, 256>>>(vi, ir, (float*)d_out);
}

// round 5
// speedup vs baseline: 1.1298x; 1.1298x over previous
#include <cuda_runtime.h>

// ---------------------------------------------------------------------------
// Net_VIF: 6 chained quadrilinear (4D) LUT interpolations, fully fused,
// bit-exact vs the JAX reference (sequential rn multiplies, corner fold
// c=0..15, separate rn mul / rn add).
//
// R5: 64B-block layout + quad-cooperative fetch + 4x4 register transpose.
//  - Each LUT repacked so the 4 corners over (b2,b3) of a cell form one
//    contiguous, 64B-aligned block (never straddles a 128B line).
//  - A quad of lanes loads one pixel's block per LDG round: every LDG's 32
//    lanes touch 8 cache lines (was 16) -> L1 wavefront traffic halved.
//  - 4x4 cross-lane transpose (shfl_xor butterfly + SEL) hands all 16
//    corners back to the owning lane. Pure bit movement: reference
//    rounding order is untouched.
// ---------------------------------------------------------------------------

#define D   17
#define D2  289
#define D3  4913
#define D4  83521
#define N_LUTS 6

// block layout: entry = cell*4 + (b2*2 + b3). 6 * 83521 * 4 * 16B ~= 32 MB.
__device__ __align__(128) float4 g_lutB[N_LUTS][D4 * 4];

__global__ void lut_pack_kernel(const float* __restrict__ s0, const float* __restrict__ s1,
                                const float* __restrict__ s2, const float* __restrict__ s3,
                                const float* __restrict__ s4, const float* __restrict__ s5) {
    int i = blockIdx.x * blockDim.x + threadIdx.x;
    if (i >= D4) return;
    int which = blockIdx.y;
    const float* src = (which == 0) ? s0 : (which == 1) ? s1 : (which == 2) ? s2
                     : (which == 3) ? s3 : (which == 4) ? s4 : s5;
    bool c4 = (which != 5);
    int i3 = i % D;
    int i2 = (i / D) % D;
#pragma unroll
    for (int e = 0; e < 4; ++e) {
        int b2 = e >> 1, b3 = e & 1;
        float4 v = make_float4(0.0f, 0.0f, 0.0f, 0.0f);
        if ((i2 + b2) <= D - 1 && (i3 + b3) <= D - 1) {
            int o = i + b2 * D + b3;
            v.x = src[o];
            v.y = src[D4 + o];
            v.z = src[2 * D4 + o];
            v.w = c4 ? src[3 * D4 + o] : 0.0f;
        }
        g_lutB[which][i * 4 + e] = v;
    }
}

// One butterfly step of the 4x4 cross-lane transpose on a register pair.
// h = (lane & m) != 0. Lanes with h=0 exchange their HI register, h=1 their LO.
__device__ __forceinline__ void xstep(float4& lo, float4& hi, bool h, int m) {
    const unsigned FULL = 0xffffffffu;
    float sx = h ? lo.x : hi.x;
    float sy = h ? lo.y : hi.y;
    float sz = h ? lo.z : hi.z;
    float sw = h ? lo.w : hi.w;
    float rx = __shfl_xor_sync(FULL, sx, m);
    float ry = __shfl_xor_sync(FULL, sy, m);
    float rz = __shfl_xor_sync(FULL, sz, m);
    float rw = __shfl_xor_sync(FULL, sw, m);
    lo.x = h ? rx : lo.x;  hi.x = h ? hi.x : rx;
    lo.y = h ? ry : lo.y;  hi.y = h ? hi.y : ry;
    lo.z = h ? rz : lo.z;  hi.z = h ? hi.z : rz;
    lo.w = h ? rw : lo.w;  hi.w = h ? hi.w : rw;
}

__device__ __forceinline__ float4 coop_stage(const float4* __restrict__ lut,
                                             float4 x, int lane) {
    const unsigned FULL = 0xffffffffu;
    const int s  = lane & 3;
    const int qb = lane & ~3;

    // Own indices / fractions (exact ops, identical to reference).
    float t0 = __saturatef(x.x) * 16.0f;
    float t1 = __saturatef(x.y) * 16.0f;
    float t2 = __saturatef(x.z) * 16.0f;
    float t3 = __saturatef(x.w) * 16.0f;
    int i0 = min((int)t0, D - 2);
    int i1 = min((int)t1, D - 2);
    int i2 = min((int)t2, D - 2);
    int i3 = min((int)t3, D - 2);
    float f0 = t0 - (float)i0;
    float f1 = t1 - (float)i1;
    float f2 = t2 - (float)i2;
    float f3 = t3 - (float)i3;
    float g0 = 1.0f - f0, g1 = 1.0f - f1, g2 = 1.0f - f2, g3 = 1.0f - f3;
    int mybase = ((i0 * D + i1) * D + i2) * D + i3;

    // Broadcast the quad's four cell bases.
    int b0v = __shfl_sync(FULL, mybase, qb);
    int b1v = __shfl_sync(FULL, mybase, qb + 1);
    int b2v = __shfl_sync(FULL, mybase, qb + 2);
    int b3v = __shfl_sync(FULL, mybase, qb + 3);

    // 16 cooperative loads: round r serves pixel qb+r; j indexes (b0,b1);
    // lane s takes element s of the 64B block (one cache line per quad).
    float4 v[4][4];
#pragma unroll
    for (int j = 0; j < 4; ++j) {
        const int oj = (j & 1) * D3 + ((j >> 1) & 1) * D2;   // b0*D3 + b1*D2
        v[0][j] = __ldg(lut + (b0v + oj) * 4 + s);
        v[1][j] = __ldg(lut + (b1v + oj) * 4 + s);
        v[2][j] = __ldg(lut + (b2v + oj) * 4 + s);
        v[3][j] = __ldg(lut + (b3v + oj) * 4 + s);
    }

    // 4x4 transpose across quad lanes (per j). Afterwards v[e][j] holds
    // element e (= b2*2 + b3) of OWN pixel's block j.
    const bool h1 = (s & 1) != 0;
    const bool h2 = (s & 2) != 0;
#pragma unroll
    for (int j = 0; j < 4; ++j) {
        xstep(v[0][j], v[1][j], h1, 1);
        xstep(v[2][j], v[3][j], h1, 1);
        xstep(v[0][j], v[2][j], h2, 2);
        xstep(v[1][j], v[3][j], h2, 2);
    }

    // Weights in the reference's exact rounding order:
    // w[c] = ((w0*w1)*w2)*w3, index c = b0 | b1<<1 | b2<<2 | b3<<3.
    float p01[4];
    p01[0] = __fmul_rn(g0, g1);
    p01[1] = __fmul_rn(f0, g1);
    p01[2] = __fmul_rn(g0, f1);
    p01[3] = __fmul_rn(f0, f1);
    float p012[8];
#pragma unroll
    for (int j = 0; j < 4; ++j) {
        p012[j]     = __fmul_rn(p01[j], g2);
        p012[4 + j] = __fmul_rn(p01[j], f2);
    }
    float w[16];
#pragma unroll
    for (int j = 0; j < 8; ++j) {
        w[j]     = __fmul_rn(p012[j], g3);
        w[8 + j] = __fmul_rn(p012[j], f3);
    }

    // Sequential fold c = 0..15 (reference order), separate rn mul / rn add.
    // c -> (j = b0+2b1 = c&3 ; e = 2*b2+b3 = 2*((c>>2)&1) + ((c>>3)&1)).
    float4 acc = make_float4(0.0f, 0.0f, 0.0f, 0.0f);
#pragma unroll
    for (int c = 0; c < 16; ++c) {
        const int j = c & 3;
        const int e = ((c >> 2) & 1) * 2 + ((c >> 3) & 1);
        const float ww = w[c];
        acc.x = __fadd_rn(acc.x, __fmul_rn(v[e][j].x, ww));
        acc.y = __fadd_rn(acc.y, __fmul_rn(v[e][j].y, ww));
        acc.z = __fadd_rn(acc.z, __fmul_rn(v[e][j].z, ww));
        acc.w = __fadd_rn(acc.w, __fmul_rn(v[e][j].w, ww));
    }
    return acc;
}

__global__ void __launch_bounds__(256, 2)
net_vif_kernel(const float* __restrict__ vi,
               const float* __restrict__ ir,
               float* __restrict__ out) {
    const int HW = 512 * 512;                  // 1<<18
    int p  = blockIdx.x * blockDim.x + threadIdx.x;
    int hw = p & (HW - 1);
    int b  = p >> 18;
    int lane = threadIdx.x & 31;

    const float* vb = vi + (size_t)b * 3 * HW + hw;
    float4 x;
    x.x = vb[0];
    x.y = vb[HW];
    x.z = vb[2 * HW];
    x.w = ir[(size_t)b * HW + hw];

    x = coop_stage(g_lutB[0], x, lane);   // lut8
    x = coop_stage(g_lutB[1], x, lane);   // lut00
    x = coop_stage(g_lutB[2], x, lane);   // lut01
    x = coop_stage(g_lutB[3], x, lane);   // lut02
    x = coop_stage(g_lutB[4], x, lane);   // lut03
    x = coop_stage(g_lutB[5], x, lane);   // lutpgf (no final clip)

    float* ob = out + (size_t)b * 3 * HW + hw;
    ob[0]      = x.x;
    ob[HW]     = x.y;
    ob[2 * HW] = x.z;
}

extern "C" void kernel_launch(void* const* d_in, const int* in_sizes, int n_in,
                              void* d_out, int out_size) {
    const float* vi = (const float*)d_in[0];   // [8,3,512,512]
    const float* ir = (const float*)d_in[1];   // [8,1,512,512]

    dim3 pg((D4 + 255) / 256, N_LUTS);
    lut_pack_kernel<<<pg, 256>>>((const float*)d_in[2], (const float*)d_in[3],
                                 (const float*)d_in[4], (const float*)d_in[5],
                                 (const float*)d_in[6], (const float*)d_in[7]);

    const int total = 8 * 512 * 512;           // 2,097,152
    net_vif_kernel<<<total / 256, 256>>>(vi, ir, (float*)d_out);
}